// round 10
// baseline (speedup 1.0000x reference)
#include <cuda_runtime.h>
#include <cuda_bf16.h>
#include <math.h>
#include <stdint.h>

#define N_NODES 100000
#define N_EDGES 1600000
#define F_IN 64
#define HDIM 200
#define N_GRAPHS 512
#define BN_EPS 1e-5f
#define NB_SCAN 98

// conversion work: x (6.4M) + 4 weight mats (132800)
#define CONV_TOTAL (N_NODES * F_IN + F_IN * HDIM + 3 * HDIM * HDIM)
#define CONV_BLOCKS ((CONV_TOTAL + 255) / 256)
#define HIST_BLOCKS ((N_EDGES / 8 + 255) / 256)

// ---------------- scratch (device globals; no allocation allowed) ----------------
__device__ int g_deg[N_NODES];        // zero-init at load; scan_block re-zeros each call
__device__ int g_excl[N_NODES];
__device__ int g_bsum[128];
__device__ int g_rowptr[N_NODES + 1];
__device__ __align__(16) int g_rank[N_EDGES];
__device__ int g_csrsrc[N_EDGES];

__device__ __align__(16) __nv_bfloat16 g_xb[(size_t)N_NODES * F_IN];
__device__ __align__(16) __nv_bfloat16 g_hin1[(size_t)N_NODES * F_IN];
__device__ __align__(16) __nv_bfloat16 g_tb[(size_t)N_NODES * HDIM];
__device__ __align__(16) __nv_bfloat16 g_h1[(size_t)N_NODES * HDIM];
__device__ __align__(16) __nv_bfloat16 g_hin2[(size_t)N_NODES * HDIM];
__device__ __align__(16) float g_h2[(size_t)N_NODES * HDIM];
__device__ __align__(16) __nv_bfloat16 g_w1a[F_IN * HDIM];
__device__ __align__(16) __nv_bfloat16 g_w1b[HDIM * HDIM];
__device__ __align__(16) __nv_bfloat16 g_w2a[HDIM * HDIM];
__device__ __align__(16) __nv_bfloat16 g_w2b[HDIM * HDIM];

// ---------------- fused conversion + edge histogram (independent halves) ----------
__global__ void convhist_kernel(const float* __restrict__ x,
                                const float* __restrict__ W1a, const float* __restrict__ W1b,
                                const float* __restrict__ W2a, const float* __restrict__ W2b,
                                const int4* __restrict__ dst4) {
    if (blockIdx.x < CONV_BLOCKS) {
        int i = blockIdx.x * 256 + threadIdx.x;
        const int XN = N_NODES * F_IN;
        const int S1 = XN + F_IN * HDIM;
        const int S2 = S1 + HDIM * HDIM;
        const int S3 = S2 + HDIM * HDIM;
        const int S4 = S3 + HDIM * HDIM;
        if (i < XN)       g_xb[i]       = __float2bfloat16(x[i]);
        else if (i < S1)  g_w1a[i - XN] = __float2bfloat16(W1a[i - XN]);
        else if (i < S2)  g_w1b[i - S1] = __float2bfloat16(W1b[i - S1]);
        else if (i < S3)  g_w2a[i - S2] = __float2bfloat16(W2a[i - S2]);
        else if (i < S4)  g_w2b[i - S3] = __float2bfloat16(W2b[i - S3]);
    } else {
        int i = (blockIdx.x - CONV_BLOCKS) * 256 + threadIdx.x;
        if (i < N_EDGES / 8) {
            int4 d0 = __ldg(dst4 + 2 * i);
            int4 d1 = __ldg(dst4 + 2 * i + 1);
            int4 r0, r1;
            r0.x = atomicAdd(&g_deg[d0.x], 1);
            r0.y = atomicAdd(&g_deg[d0.y], 1);
            r0.z = atomicAdd(&g_deg[d0.z], 1);
            r0.w = atomicAdd(&g_deg[d0.w], 1);
            r1.x = atomicAdd(&g_deg[d1.x], 1);
            r1.y = atomicAdd(&g_deg[d1.y], 1);
            r1.z = atomicAdd(&g_deg[d1.z], 1);
            r1.w = atomicAdd(&g_deg[d1.w], 1);
            ((int4*)g_rank)[2 * i] = r0;
            ((int4*)g_rank)[2 * i + 1] = r1;
        }
    }
}

// ---------------- CSR scan (g_deg consumed AND re-zeroed here) ----------------
__global__ void scan_block_kernel() {
    __shared__ int ws[32];
    int i = blockIdx.x * 1024 + threadIdx.x;
    int v = 0;
    if (i < N_NODES) {
        v = g_deg[i];
        g_deg[i] = 0;  // reset for next kernel_launch invocation (replaces memset)
    }
    int lane = threadIdx.x & 31, wid = threadIdx.x >> 5;
    int s = v;
#pragma unroll
    for (int off = 1; off < 32; off <<= 1) {
        int n = __shfl_up_sync(0xFFFFFFFFu, s, off);
        if (lane >= off) s += n;
    }
    if (lane == 31) ws[wid] = s;
    __syncthreads();
    if (wid == 0) {
        int t = ws[lane];
#pragma unroll
        for (int off = 1; off < 32; off <<= 1) {
            int n = __shfl_up_sync(0xFFFFFFFFu, t, off);
            if (lane >= off) t += n;
        }
        ws[lane] = t;
    }
    __syncthreads();
    int pre = (wid > 0) ? ws[wid - 1] : 0;
    if (i < N_NODES) g_excl[i] = pre + s - v;
    if (threadIdx.x == 1023) g_bsum[blockIdx.x] = ws[31];
}

__global__ void scan_apply_kernel() {
    __shared__ int pre[NB_SCAN];
    if (threadIdx.x == 0) {
        int run = 0;
#pragma unroll
        for (int b = 0; b < NB_SCAN; b++) {
            int t = g_bsum[b];
            pre[b] = run;
            run += t;
        }
    }
    __syncthreads();
    int i = blockIdx.x * blockDim.x + threadIdx.x;
    if (i < N_NODES) g_rowptr[i] = g_excl[i] + pre[i >> 10];
    if (i == 0) g_rowptr[N_NODES] = N_EDGES;
}

// atomic-free fill: position = rowptr[dst] + rank
__global__ void fill_kernel(const int4* __restrict__ src4, const int4* __restrict__ dst4) {
    int i = blockIdx.x * blockDim.x + threadIdx.x;
    if (i < N_EDGES / 8) {
        int4 s0 = __ldg(src4 + 2 * i);
        int4 d0 = __ldg(dst4 + 2 * i);
        int4 r0 = ((const int4*)g_rank)[2 * i];
        int4 s1 = __ldg(src4 + 2 * i + 1);
        int4 d1 = __ldg(dst4 + 2 * i + 1);
        int4 r1 = ((const int4*)g_rank)[2 * i + 1];
        g_csrsrc[g_rowptr[d0.x] + r0.x] = s0.x;
        g_csrsrc[g_rowptr[d0.y] + r0.y] = s0.y;
        g_csrsrc[g_rowptr[d0.z] + r0.z] = s0.z;
        g_csrsrc[g_rowptr[d0.w] + r0.w] = s0.w;
        g_csrsrc[g_rowptr[d1.x] + r1.x] = s1.x;
        g_csrsrc[g_rowptr[d1.y] + r1.y] = s1.y;
        g_csrsrc[g_rowptr[d1.z] + r1.z] = s1.z;
        g_csrsrc[g_rowptr[d1.w] + r1.w] = s1.w;
    }
}

// ---------------- GIN aggregation (bf16 in, fp32 accumulate, bf16 out) ----------
__global__ void agg64_kernel(const __nv_bfloat16* __restrict__ X, const float* __restrict__ epsp,
                             __nv_bfloat16* __restrict__ out) {
    int w = (blockIdx.x * blockDim.x + threadIdx.x) >> 5;
    int lane = threadIdx.x & 31;
    if (w >= N_NODES) return;
    float2 a0 = {0.f, 0.f}, a1 = {0.f, 0.f}, a2 = {0.f, 0.f}, a3 = {0.f, 0.f};
    int beg = g_rowptr[w], end = g_rowptr[w + 1];
    int e = beg;
    for (; e + 4 <= end; e += 4) {
        int s0 = g_csrsrc[e], s1 = g_csrsrc[e + 1], s2 = g_csrsrc[e + 2], s3 = g_csrsrc[e + 3];
        float2 f0 = __bfloat1622float2(__ldg((const __nv_bfloat162*)(X + (size_t)s0 * F_IN) + lane));
        float2 f1 = __bfloat1622float2(__ldg((const __nv_bfloat162*)(X + (size_t)s1 * F_IN) + lane));
        float2 f2 = __bfloat1622float2(__ldg((const __nv_bfloat162*)(X + (size_t)s2 * F_IN) + lane));
        float2 f3 = __bfloat1622float2(__ldg((const __nv_bfloat162*)(X + (size_t)s3 * F_IN) + lane));
        a0.x += f0.x; a0.y += f0.y;
        a1.x += f1.x; a1.y += f1.y;
        a2.x += f2.x; a2.y += f2.y;
        a3.x += f3.x; a3.y += f3.y;
    }
    for (; e < end; e++) {
        int s = g_csrsrc[e];
        float2 f = __bfloat1622float2(__ldg((const __nv_bfloat162*)(X + (size_t)s * F_IN) + lane));
        a0.x += f.x; a0.y += f.y;
    }
    float2 acc = {a0.x + a1.x + a2.x + a3.x, a0.y + a1.y + a2.y + a3.y};
    float ep = 1.f + *epsp;
    float2 xi = __bfloat1622float2(*((const __nv_bfloat162*)(X + (size_t)w * F_IN) + lane));
    *(((__nv_bfloat162*)(out + (size_t)w * F_IN)) + lane) =
        __floats2bfloat162_rn(ep * xi.x + acc.x, ep * xi.y + acc.y);
}

__device__ __forceinline__ void add8(float* a, uint4 v) {
    __nv_bfloat162 p0 = *(__nv_bfloat162*)&v.x;
    __nv_bfloat162 p1 = *(__nv_bfloat162*)&v.y;
    __nv_bfloat162 p2 = *(__nv_bfloat162*)&v.z;
    __nv_bfloat162 p3 = *(__nv_bfloat162*)&v.w;
    float2 f0 = __bfloat1622float2(p0), f1 = __bfloat1622float2(p1);
    float2 f2 = __bfloat1622float2(p2), f3 = __bfloat1622float2(p3);
    a[0] += f0.x; a[1] += f0.y; a[2] += f1.x; a[3] += f1.y;
    a[4] += f2.x; a[5] += f2.y; a[6] += f3.x; a[7] += f3.y;
}

__global__ void agg200_kernel(const __nv_bfloat16* __restrict__ X, const float* __restrict__ epsp,
                              __nv_bfloat16* __restrict__ out) {
    int w = (blockIdx.x * blockDim.x + threadIdx.x) >> 5;
    int lane = threadIdx.x & 31;
    if (w >= N_NODES) return;
    bool act = lane < 25;
    float a[8] = {0.f, 0.f, 0.f, 0.f, 0.f, 0.f, 0.f, 0.f};
    int beg = g_rowptr[w], end = g_rowptr[w + 1];
    int e = beg;
    for (; e + 4 <= end; e += 4) {
        int s0 = g_csrsrc[e], s1 = g_csrsrc[e + 1], s2 = g_csrsrc[e + 2], s3 = g_csrsrc[e + 3];
        if (act) {
            uint4 v0 = __ldg((const uint4*)(X + (size_t)s0 * HDIM) + lane);
            uint4 v1 = __ldg((const uint4*)(X + (size_t)s1 * HDIM) + lane);
            uint4 v2 = __ldg((const uint4*)(X + (size_t)s2 * HDIM) + lane);
            uint4 v3 = __ldg((const uint4*)(X + (size_t)s3 * HDIM) + lane);
            add8(a, v0);
            add8(a, v1);
            add8(a, v2);
            add8(a, v3);
        }
    }
    for (; e < end; e++) {
        int s = g_csrsrc[e];
        if (act) add8(a, __ldg((const uint4*)(X + (size_t)s * HDIM) + lane));
    }
    if (!act) return;
    float ep = 1.f + *epsp;
    float xs[8] = {0.f, 0.f, 0.f, 0.f, 0.f, 0.f, 0.f, 0.f};
    add8(xs, *((const uint4*)(X + (size_t)w * HDIM) + lane));
    float r[8];
#pragma unroll
    for (int j = 0; j < 8; j++) r[j] = ep * xs[j] + a[j];
    uint4 u;
    __nv_bfloat162 p0 = __floats2bfloat162_rn(r[0], r[1]);
    __nv_bfloat162 p1 = __floats2bfloat162_rn(r[2], r[3]);
    __nv_bfloat162 p2 = __floats2bfloat162_rn(r[4], r[5]);
    __nv_bfloat162 p3 = __floats2bfloat162_rn(r[6], r[7]);
    u.x = *(uint32_t*)&p0; u.y = *(uint32_t*)&p1;
    u.z = *(uint32_t*)&p2; u.w = *(uint32_t*)&p3;
    *((uint4*)(out + (size_t)w * HDIM) + lane) = u;
}

// ---------------- bf16 tensor-core GEMM: BK=32, 3-stage pipeline, 1 sync/stage ------
__device__ __forceinline__ uint32_t s2u(const void* p) {
    return (uint32_t)__cvta_generic_to_shared(p);
}

__device__ __forceinline__ void cpasync16(uint32_t dst, const void* src, int bytes) {
    asm volatile("cp.async.cg.shared.global [%0], [%1], 16, %2;\n"
                 :: "r"(dst), "l"(src), "r"(bytes));
}

__device__ __forceinline__ void mma_bf16(float* c, const uint32_t* a, uint32_t b0, uint32_t b1) {
    asm volatile(
        "mma.sync.aligned.m16n8k16.row.col.f32.bf16.bf16.f32 "
        "{%0,%1,%2,%3},{%4,%5,%6,%7},{%8,%9},{%0,%1,%2,%3};"
        : "+f"(c[0]), "+f"(c[1]), "+f"(c[2]), "+f"(c[3])
        : "r"(a[0]), "r"(a[1]), "r"(a[2]), "r"(a[3]), "r"(b0), "r"(b1));
}

#define GEMM_SMEM_BYTES ((3 * 5120 + 3 * 4352) * 2)

// EPI 0: relu(acc + bias); EPI 1: bn(relu(acc + bias))
template <int EPI, bool OUT_BF16>
__global__ __launch_bounds__(256) void gemm_bf16_kernel(
    const __nv_bfloat16* __restrict__ A, const __nv_bfloat16* __restrict__ B,
    const float* __restrict__ bias,
    const float* __restrict__ gamma, const float* __restrict__ beta,
    const float* __restrict__ mean, const float* __restrict__ var,
    void* __restrict__ Cv, int M, int K, int N) {
    extern __shared__ __align__(16) __nv_bfloat16 sm[];

    int tid = threadIdx.x;
    int lane = tid & 31, wid = tid >> 5;
    int warp_m = wid & 3, warp_n = wid >> 2;
    int row0 = blockIdx.x * 128, col0 = blockIdx.y * 128;
    int g = lane >> 2, t4 = lane & 3;

    float acc[2][8][4];
#pragma unroll
    for (int mt = 0; mt < 2; mt++)
#pragma unroll
        for (int nt = 0; nt < 8; nt++)
#pragma unroll
            for (int i = 0; i < 4; i++) acc[mt][nt][i] = 0.f;

    int la_m = tid >> 1, la_k = (tid & 1) * 16;
    int ar = row0 + la_m;
    const __nv_bfloat16* aRow = A + (size_t)(ar < M ? ar : 0) * K;
    int lb_r = tid >> 4, lb_c = (tid & 15) * 8;
    bool bcol_ok = (col0 + lb_c) < N;

    uint32_t smbase = s2u(sm);
    int nk = (K + 31) / 32;

#define LOADSTAGE(kt)                                                              \
    {                                                                              \
        int bi_ = (kt) % 3;                                                        \
        uint32_t adst = smbase + (uint32_t)(bi_ * 5120 + la_m * 40 + la_k) * 2;    \
        int ka0 = (kt) * 32 + la_k;                                                \
        int ab0 = (ar < M && ka0 < K) ? 16 : 0;                                    \
        int ab1 = (ar < M && ka0 + 8 < K) ? 16 : 0;                                \
        cpasync16(adst, aRow + (ab0 ? ka0 : 0), ab0);                              \
        cpasync16(adst + 16, aRow + (ab1 ? ka0 + 8 : 0), ab1);                     \
        uint32_t bdst = smbase + (uint32_t)(15360 + bi_ * 4352 + lb_r * 136 + lb_c) * 2; \
        int kb0 = (kt) * 32 + lb_r;                                                \
        int bb0 = (kb0 < K && bcol_ok) ? 16 : 0;                                   \
        int bb1 = (kb0 + 16 < K && bcol_ok) ? 16 : 0;                              \
        cpasync16(bdst, B + (size_t)(bb0 ? kb0 : 0) * N + col0 + lb_c, bb0);       \
        cpasync16(bdst + 16 * 136 * 2,                                             \
                  B + (size_t)(bb1 ? kb0 + 16 : 0) * N + col0 + lb_c, bb1);        \
        asm volatile("cp.async.commit_group;\n");                                  \
    }

    LOADSTAGE(0);
    if (nk > 1) LOADSTAGE(1);

    for (int kt = 0; kt < nk; kt++) {
        if (kt == nk - 1) {
            asm volatile("cp.async.wait_group 0;\n");
        } else {
            asm volatile("cp.async.wait_group 1;\n");
        }
        __syncthreads();
        if (kt + 2 < nk) LOADSTAGE(kt + 2);

        int bi = kt % 3;
        uint32_t abase = smbase + (uint32_t)(bi * 5120) * 2;
        uint32_t bbase = smbase + (uint32_t)(15360 + bi * 4352) * 2;
#pragma unroll
        for (int k16 = 0; k16 < 2; k16++) {
            if (kt * 32 + k16 * 16 >= K) break;
            uint32_t af[2][4];
            int arow_f = warp_m * 32 + (lane & 15);
#pragma unroll
            for (int mt = 0; mt < 2; mt++) {
                uint32_t addr = abase + (uint32_t)((arow_f + mt * 16) * 80 + k16 * 32 +
                                                   (lane >> 4) * 16);
                asm volatile("ldmatrix.sync.aligned.m8n8.x4.shared.b16 {%0,%1,%2,%3}, [%4];"
                             : "=r"(af[mt][0]), "=r"(af[mt][1]), "=r"(af[mt][2]), "=r"(af[mt][3])
                             : "r"(addr));
            }
            uint32_t bb[4][4];
#pragma unroll
            for (int p = 0; p < 4; p++) {
                uint32_t addr = bbase + (uint32_t)((k16 * 16 + (lane & 15)) * 272 +
                                                   (warp_n * 64 + p * 16 + (lane >> 4) * 8) * 2);
                asm volatile("ldmatrix.sync.aligned.m8n8.x4.trans.shared.b16 {%0,%1,%2,%3}, [%4];"
                             : "=r"(bb[p][0]), "=r"(bb[p][1]), "=r"(bb[p][2]), "=r"(bb[p][3])
                             : "r"(addr));
            }
#pragma unroll
            for (int nt = 0; nt < 8; nt++) {
                uint32_t b0 = bb[nt >> 1][(nt & 1) * 2];
                uint32_t b1 = bb[nt >> 1][(nt & 1) * 2 + 1];
                mma_bf16(acc[0][nt], af[0], b0, b1);
                mma_bf16(acc[1][nt], af[1], b0, b1);
            }
        }
    }
#undef LOADSTAGE

#pragma unroll
    for (int nt = 0; nt < 8; nt++) {
        int col = col0 + warp_n * 64 + nt * 8 + 2 * t4;
        if (col >= N) continue;
        float bi0 = bias[col], bi1 = bias[col + 1];
        float s0 = 1.f, s1 = 1.f, o0 = 0.f, o1 = 0.f;
        if (EPI == 1) {
            s0 = rsqrtf(var[col] + BN_EPS) * gamma[col];
            s1 = rsqrtf(var[col + 1] + BN_EPS) * gamma[col + 1];
            o0 = beta[col] - mean[col] * s0;
            o1 = beta[col + 1] - mean[col + 1] * s1;
        }
#pragma unroll
        for (int mt = 0; mt < 2; mt++) {
#pragma unroll
            for (int h = 0; h < 2; h++) {
                int r = row0 + warp_m * 32 + mt * 16 + g + h * 8;
                if (r >= M) continue;
                float v0 = fmaxf(acc[mt][nt][2 * h + 0] + bi0, 0.f);
                float v1 = fmaxf(acc[mt][nt][2 * h + 1] + bi1, 0.f);
                if (EPI == 1) { v0 = v0 * s0 + o0; v1 = v1 * s1 + o1; }
                if (OUT_BF16) {
                    *(__nv_bfloat162*)((__nv_bfloat16*)Cv + (size_t)r * N + col) =
                        __floats2bfloat162_rn(v0, v1);
                } else {
                    *(float2*)((float*)Cv + (size_t)r * N + col) = make_float2(v0, v1);
                }
            }
        }
    }
}

// ---------------- fused pooling + FC + log_softmax ----------------
__global__ __launch_bounds__(256) void poolfc_kernel(const int* __restrict__ batch,
                                                     const float* __restrict__ Wfc,
                                                     const float* __restrict__ bfc,
                                                     float* __restrict__ out) {
    int gid = blockIdx.x;
    int f = threadIdx.x;
    __shared__ int sb[2];
    __shared__ float red0[8], red1[8];
    if (f < 2) {
        int tgt = gid + f;
        int lo = 0, hi = N_NODES;
        while (lo < hi) {
            int mid = (lo + hi) >> 1;
            if (batch[mid] < tgt) lo = mid + 1; else hi = mid;
        }
        sb[f] = lo;
    }
    __syncthreads();
    int beg = sb[0], end = sb[1];
    float l0 = 0.f, l1 = 0.f;
    if (f < HDIM) {
        float s = 0.f, m = -INFINITY;
        for (int i = beg; i < end; i++) {
            float v = g_h2[(size_t)i * HDIM + f];
            s += v;
            m = fmaxf(m, v);
        }
        l0 = s * Wfc[f * 2 + 0] + m * Wfc[(HDIM + f) * 2 + 0];
        l1 = s * Wfc[f * 2 + 1] + m * Wfc[(HDIM + f) * 2 + 1];
    }
#pragma unroll
    for (int off = 16; off; off >>= 1) {
        l0 += __shfl_down_sync(0xFFFFFFFFu, l0, off);
        l1 += __shfl_down_sync(0xFFFFFFFFu, l1, off);
    }
    int lane = f & 31, wid = f >> 5;
    if (lane == 0) { red0[wid] = l0; red1[wid] = l1; }
    __syncthreads();
    if (f == 0) {
        float t0 = 0.f, t1 = 0.f;
#pragma unroll
        for (int wi = 0; wi < 8; wi++) { t0 += red0[wi]; t1 += red1[wi]; }
        t0 += bfc[0];
        t1 += bfc[1];
        float m = fmaxf(t0, t1);
        float lse = m + logf(expf(t0 - m) + expf(t1 - m));
        out[gid * 2 + 0] = t0 - lse;
        out[gid * 2 + 1] = t1 - lse;
    }
}

// ---------------- launch ----------------
extern "C" void kernel_launch(void* const* d_in, const int* in_sizes, int n_in,
                              void* d_out, int out_size) {
    const float* x    = (const float*)d_in[0];
    const int*   ei   = (const int*)d_in[1];
    const int*   batch = (const int*)d_in[2];
    const float* eps1 = (const float*)d_in[3];
    const float* W1a  = (const float*)d_in[4];
    const float* b1a  = (const float*)d_in[5];
    const float* W1b  = (const float*)d_in[6];
    const float* b1b  = (const float*)d_in[7];
    const float* bn1g = (const float*)d_in[8];
    const float* bn1b = (const float*)d_in[9];
    const float* bn1m = (const float*)d_in[10];
    const float* bn1v = (const float*)d_in[11];
    const float* eps2 = (const float*)d_in[12];
    const float* W2a  = (const float*)d_in[13];
    const float* b2a  = (const float*)d_in[14];
    const float* W2b  = (const float*)d_in[15];
    const float* b2b  = (const float*)d_in[16];
    const float* bn2g = (const float*)d_in[17];
    const float* bn2b = (const float*)d_in[18];
    const float* bn2m = (const float*)d_in[19];
    const float* bn2v = (const float*)d_in[20];
    const float* Wfc  = (const float*)d_in[21];
    const float* bfc  = (const float*)d_in[22];
    float* out = (float*)d_out;

    const int* src = ei;
    const int* dst = ei + N_EDGES;

    __nv_bfloat16 *xb, *hin1, *tb, *h1, *hin2, *w1a, *w1b, *w2a, *w2b;
    float* h2;
    cudaGetSymbolAddress((void**)&xb,   g_xb);
    cudaGetSymbolAddress((void**)&hin1, g_hin1);
    cudaGetSymbolAddress((void**)&tb,   g_tb);
    cudaGetSymbolAddress((void**)&h1,   g_h1);
    cudaGetSymbolAddress((void**)&hin2, g_hin2);
    cudaGetSymbolAddress((void**)&h2,   g_h2);
    cudaGetSymbolAddress((void**)&w1a,  g_w1a);
    cudaGetSymbolAddress((void**)&w1b,  g_w1b);
    cudaGetSymbolAddress((void**)&w2a,  g_w2a);
    cudaGetSymbolAddress((void**)&w2b,  g_w2b);

    cudaFuncSetAttribute(gemm_bf16_kernel<0, true>,
                         cudaFuncAttributeMaxDynamicSharedMemorySize, GEMM_SMEM_BYTES);
    cudaFuncSetAttribute(gemm_bf16_kernel<1, true>,
                         cudaFuncAttributeMaxDynamicSharedMemorySize, GEMM_SMEM_BYTES);
    cudaFuncSetAttribute(gemm_bf16_kernel<1, false>,
                         cudaFuncAttributeMaxDynamicSharedMemorySize, GEMM_SMEM_BYTES);

    const int TPB = 256;
    int nbEdges8 = (N_EDGES / 8 + TPB - 1) / TPB;
    int nbNodes = (N_NODES + TPB - 1) / TPB;
    int nbWarpNodes = (N_NODES * 32 + TPB - 1) / TPB;
    dim3 gemm_grid((N_NODES + 127) / 128, 2);

    // (1) fused conversions + edge histogram (g_deg zero at entry: load-init or scan reset)
    convhist_kernel<<<CONV_BLOCKS + HIST_BLOCKS, TPB>>>(x, W1a, W1b, W2a, W2b, (const int4*)dst);
    // (2)(3) CSR scan; scan_block re-zeros g_deg for the next invocation
    scan_block_kernel<<<NB_SCAN, 1024>>>();
    scan_apply_kernel<<<nbNodes, TPB>>>();
    // (4) atomic-free fill
    fill_kernel<<<nbEdges8, TPB>>>((const int4*)src, (const int4*)dst);
    // (5) layer-1 aggregation
    agg64_kernel<<<nbWarpNodes, TPB>>>(xb, eps1, hin1);

    // (6) Layer 1 GEMM a  <-- ncu -s 5 -c 1 profiles this launch
    gemm_bf16_kernel<0, true><<<gemm_grid, 256, GEMM_SMEM_BYTES>>>(
        hin1, w1a, b1a, nullptr, nullptr, nullptr, nullptr, tb, N_NODES, F_IN, HDIM);
    gemm_bf16_kernel<1, true><<<gemm_grid, 256, GEMM_SMEM_BYTES>>>(
        tb, w1b, b1b, bn1g, bn1b, bn1m, bn1v, h1, N_NODES, HDIM, HDIM);

    // Layer 2
    agg200_kernel<<<nbWarpNodes, TPB>>>(h1, eps2, hin2);
    gemm_bf16_kernel<0, true><<<gemm_grid, 256, GEMM_SMEM_BYTES>>>(
        hin2, w2a, b2a, nullptr, nullptr, nullptr, nullptr, tb, N_NODES, HDIM, HDIM);
    gemm_bf16_kernel<1, false><<<gemm_grid, 256, GEMM_SMEM_BYTES>>>(
        tb, w2b, b2b, bn2g, bn2b, bn2m, bn2v, h2, N_NODES, HDIM, HDIM);

    // fused pooling + FC + log_softmax
    poolfc_kernel<<<N_GRAPHS, 256>>>(batch, Wfc, bfc, out);
}

// round 12
// speedup vs baseline: 1.0398x; 1.0398x over previous
#include <cuda_runtime.h>
#include <cuda_bf16.h>
#include <math.h>
#include <stdint.h>

#define N_NODES 100000
#define N_EDGES 1600000
#define F_IN 64
#define HDIM 200
#define N_GRAPHS 512
#define BN_EPS 1e-5f
#define NB_SCAN 98

#define CONV_TOTAL (N_NODES * F_IN + F_IN * HDIM + 3 * HDIM * HDIM)
#define CONV_BLOCKS ((CONV_TOTAL + 255) / 256)
#define HIST_BLOCKS ((N_EDGES / 8 + 255) / 256)

#define GEMM_SMEM_BYTES ((3 * 5120 + 3 * 4352) * 2)

// ---------------- scratch (device globals; no allocation allowed) ----------------
__device__ int g_deg[N_NODES];        // zero-init at load; scan_block re-zeros each call
__device__ int g_excl[N_NODES];
__device__ int g_bsum[128];
__device__ int g_rowptr[N_NODES + 1];
__device__ __align__(16) int g_rank[N_EDGES];
__device__ int g_csrsrc[N_EDGES];

__device__ __align__(16) __nv_bfloat16 g_xb[(size_t)N_NODES * F_IN];
__device__ __align__(16) __nv_bfloat16 g_hin1[(size_t)N_NODES * F_IN];
__device__ __align__(16) __nv_bfloat16 g_tb[(size_t)N_NODES * HDIM];
__device__ __align__(16) __nv_bfloat16 g_h1[(size_t)N_NODES * HDIM];
__device__ __align__(16) __nv_bfloat16 g_hin2[(size_t)N_NODES * HDIM];
__device__ __align__(16) float g_h2[(size_t)N_NODES * HDIM];
__device__ __align__(16) __nv_bfloat16 g_w1a[F_IN * HDIM];
__device__ __align__(16) __nv_bfloat16 g_w1b[HDIM * HDIM];
__device__ __align__(16) __nv_bfloat16 g_w2a[HDIM * HDIM];
__device__ __align__(16) __nv_bfloat16 g_w2b[HDIM * HDIM];

// ---------------- fused conversion + edge histogram ----------
__global__ void convhist_kernel(const float* __restrict__ x,
                                const float* __restrict__ W1a, const float* __restrict__ W1b,
                                const float* __restrict__ W2a, const float* __restrict__ W2b,
                                const int4* __restrict__ dst4) {
    if (blockIdx.x < CONV_BLOCKS) {
        int i = blockIdx.x * 256 + threadIdx.x;
        const int XN = N_NODES * F_IN;
        const int S1 = XN + F_IN * HDIM;
        const int S2 = S1 + HDIM * HDIM;
        const int S3 = S2 + HDIM * HDIM;
        const int S4 = S3 + HDIM * HDIM;
        if (i < XN)       g_xb[i]       = __float2bfloat16(x[i]);
        else if (i < S1)  g_w1a[i - XN] = __float2bfloat16(W1a[i - XN]);
        else if (i < S2)  g_w1b[i - S1] = __float2bfloat16(W1b[i - S1]);
        else if (i < S3)  g_w2a[i - S2] = __float2bfloat16(W2a[i - S2]);
        else if (i < S4)  g_w2b[i - S3] = __float2bfloat16(W2b[i - S3]);
    } else {
        int i = (blockIdx.x - CONV_BLOCKS) * 256 + threadIdx.x;
        if (i < N_EDGES / 8) {
            int4 d0 = __ldg(dst4 + 2 * i);
            int4 d1 = __ldg(dst4 + 2 * i + 1);
            int4 r0, r1;
            r0.x = atomicAdd(&g_deg[d0.x], 1);
            r0.y = atomicAdd(&g_deg[d0.y], 1);
            r0.z = atomicAdd(&g_deg[d0.z], 1);
            r0.w = atomicAdd(&g_deg[d0.w], 1);
            r1.x = atomicAdd(&g_deg[d1.x], 1);
            r1.y = atomicAdd(&g_deg[d1.y], 1);
            r1.z = atomicAdd(&g_deg[d1.z], 1);
            r1.w = atomicAdd(&g_deg[d1.w], 1);
            ((int4*)g_rank)[2 * i] = r0;
            ((int4*)g_rank)[2 * i + 1] = r1;
        }
    }
}

// ---------------- CSR scan ----------------
__global__ void scan_block_kernel() {
    __shared__ int ws[32];
    int i = blockIdx.x * 1024 + threadIdx.x;
    int v = 0;
    if (i < N_NODES) {
        v = g_deg[i];
        g_deg[i] = 0;
    }
    int lane = threadIdx.x & 31, wid = threadIdx.x >> 5;
    int s = v;
#pragma unroll
    for (int off = 1; off < 32; off <<= 1) {
        int n = __shfl_up_sync(0xFFFFFFFFu, s, off);
        if (lane >= off) s += n;
    }
    if (lane == 31) ws[wid] = s;
    __syncthreads();
    if (wid == 0) {
        int t = ws[lane];
#pragma unroll
        for (int off = 1; off < 32; off <<= 1) {
            int n = __shfl_up_sync(0xFFFFFFFFu, t, off);
            if (lane >= off) t += n;
        }
        ws[lane] = t;
    }
    __syncthreads();
    int pre = (wid > 0) ? ws[wid - 1] : 0;
    if (i < N_NODES) g_excl[i] = pre + s - v;
    if (threadIdx.x == 1023) g_bsum[blockIdx.x] = ws[31];
}

__global__ void scan_apply_kernel() {
    __shared__ int pre[NB_SCAN];
    if (threadIdx.x == 0) {
        int run = 0;
#pragma unroll
        for (int b = 0; b < NB_SCAN; b++) {
            int t = g_bsum[b];
            pre[b] = run;
            run += t;
        }
    }
    __syncthreads();
    int i = blockIdx.x * blockDim.x + threadIdx.x;
    if (i < N_NODES) g_rowptr[i] = g_excl[i] + pre[i >> 10];
    if (i == 0) g_rowptr[N_NODES] = N_EDGES;
}

__global__ void fill_kernel(const int4* __restrict__ src4, const int4* __restrict__ dst4) {
    int i = blockIdx.x * blockDim.x + threadIdx.x;
    if (i < N_EDGES / 8) {
        int4 s0 = __ldg(src4 + 2 * i);
        int4 d0 = __ldg(dst4 + 2 * i);
        int4 r0 = ((const int4*)g_rank)[2 * i];
        int4 s1 = __ldg(src4 + 2 * i + 1);
        int4 d1 = __ldg(dst4 + 2 * i + 1);
        int4 r1 = ((const int4*)g_rank)[2 * i + 1];
        g_csrsrc[g_rowptr[d0.x] + r0.x] = s0.x;
        g_csrsrc[g_rowptr[d0.y] + r0.y] = s0.y;
        g_csrsrc[g_rowptr[d0.z] + r0.z] = s0.z;
        g_csrsrc[g_rowptr[d0.w] + r0.w] = s0.w;
        g_csrsrc[g_rowptr[d1.x] + r1.x] = s1.x;
        g_csrsrc[g_rowptr[d1.y] + r1.y] = s1.y;
        g_csrsrc[g_rowptr[d1.z] + r1.z] = s1.z;
        g_csrsrc[g_rowptr[d1.w] + r1.w] = s1.w;
    }
}

// ---------------- GIN aggregation (bf16 in, fp32 accumulate, bf16 out) ----------
__global__ void agg64_kernel(const __nv_bfloat16* __restrict__ X, const float* __restrict__ epsp,
                             __nv_bfloat16* __restrict__ out) {
    int w = (blockIdx.x * blockDim.x + threadIdx.x) >> 5;
    int lane = threadIdx.x & 31;
    if (w >= N_NODES) return;
    float2 a0 = {0.f, 0.f}, a1 = {0.f, 0.f}, a2 = {0.f, 0.f}, a3 = {0.f, 0.f};
    int beg = g_rowptr[w], end = g_rowptr[w + 1];
    int e = beg;
    for (; e + 4 <= end; e += 4) {
        int s0 = g_csrsrc[e], s1 = g_csrsrc[e + 1], s2 = g_csrsrc[e + 2], s3 = g_csrsrc[e + 3];
        float2 f0 = __bfloat1622float2(__ldg((const __nv_bfloat162*)(X + (size_t)s0 * F_IN) + lane));
        float2 f1 = __bfloat1622float2(__ldg((const __nv_bfloat162*)(X + (size_t)s1 * F_IN) + lane));
        float2 f2 = __bfloat1622float2(__ldg((const __nv_bfloat162*)(X + (size_t)s2 * F_IN) + lane));
        float2 f3 = __bfloat1622float2(__ldg((const __nv_bfloat162*)(X + (size_t)s3 * F_IN) + lane));
        a0.x += f0.x; a0.y += f0.y;
        a1.x += f1.x; a1.y += f1.y;
        a2.x += f2.x; a2.y += f2.y;
        a3.x += f3.x; a3.y += f3.y;
    }
    for (; e < end; e++) {
        int s = g_csrsrc[e];
        float2 f = __bfloat1622float2(__ldg((const __nv_bfloat162*)(X + (size_t)s * F_IN) + lane));
        a0.x += f.x; a0.y += f.y;
    }
    float2 acc = {a0.x + a1.x + a2.x + a3.x, a0.y + a1.y + a2.y + a3.y};
    float ep = 1.f + *epsp;
    float2 xi = __bfloat1622float2(*((const __nv_bfloat162*)(X + (size_t)w * F_IN) + lane));
    *(((__nv_bfloat162*)(out + (size_t)w * F_IN)) + lane) =
        __floats2bfloat162_rn(ep * xi.x + acc.x, ep * xi.y + acc.y);
}

__device__ __forceinline__ void add8(float* a, uint4 v) {
    __nv_bfloat162 p0 = *(__nv_bfloat162*)&v.x;
    __nv_bfloat162 p1 = *(__nv_bfloat162*)&v.y;
    __nv_bfloat162 p2 = *(__nv_bfloat162*)&v.z;
    __nv_bfloat162 p3 = *(__nv_bfloat162*)&v.w;
    float2 f0 = __bfloat1622float2(p0), f1 = __bfloat1622float2(p1);
    float2 f2 = __bfloat1622float2(p2), f3 = __bfloat1622float2(p3);
    a[0] += f0.x; a[1] += f0.y; a[2] += f1.x; a[3] += f1.y;
    a[4] += f2.x; a[5] += f2.y; a[6] += f3.x; a[7] += f3.y;
}

__global__ void agg200_kernel(const __nv_bfloat16* __restrict__ X, const float* __restrict__ epsp,
                              __nv_bfloat16* __restrict__ out) {
    int w = (blockIdx.x * blockDim.x + threadIdx.x) >> 5;
    int lane = threadIdx.x & 31;
    if (w >= N_NODES) return;
    bool act = lane < 25;
    float a[8] = {0.f, 0.f, 0.f, 0.f, 0.f, 0.f, 0.f, 0.f};
    int beg = g_rowptr[w], end = g_rowptr[w + 1];
    int e = beg;
    for (; e + 4 <= end; e += 4) {
        int s0 = g_csrsrc[e], s1 = g_csrsrc[e + 1], s2 = g_csrsrc[e + 2], s3 = g_csrsrc[e + 3];
        if (act) {
            uint4 v0 = __ldg((const uint4*)(X + (size_t)s0 * HDIM) + lane);
            uint4 v1 = __ldg((const uint4*)(X + (size_t)s1 * HDIM) + lane);
            uint4 v2 = __ldg((const uint4*)(X + (size_t)s2 * HDIM) + lane);
            uint4 v3 = __ldg((const uint4*)(X + (size_t)s3 * HDIM) + lane);
            add8(a, v0);
            add8(a, v1);
            add8(a, v2);
            add8(a, v3);
        }
    }
    for (; e < end; e++) {
        int s = g_csrsrc[e];
        if (act) add8(a, __ldg((const uint4*)(X + (size_t)s * HDIM) + lane));
    }
    if (!act) return;
    float ep = 1.f + *epsp;
    float xs[8] = {0.f, 0.f, 0.f, 0.f, 0.f, 0.f, 0.f, 0.f};
    add8(xs, *((const uint4*)(X + (size_t)w * HDIM) + lane));
    float r[8];
#pragma unroll
    for (int j = 0; j < 8; j++) r[j] = ep * xs[j] + a[j];
    uint4 u;
    __nv_bfloat162 p0 = __floats2bfloat162_rn(r[0], r[1]);
    __nv_bfloat162 p1 = __floats2bfloat162_rn(r[2], r[3]);
    __nv_bfloat162 p2 = __floats2bfloat162_rn(r[4], r[5]);
    __nv_bfloat162 p3 = __floats2bfloat162_rn(r[6], r[7]);
    u.x = *(uint32_t*)&p0; u.y = *(uint32_t*)&p1;
    u.z = *(uint32_t*)&p2; u.w = *(uint32_t*)&p3;
    *((uint4*)(out + (size_t)w * HDIM) + lane) = u;
}

// ---------------- GEMM pass (verbatim R9 pipeline, NTC-templated warp tile) -------
__device__ __forceinline__ uint32_t s2u(const void* p) {
    return (uint32_t)__cvta_generic_to_shared(p);
}

__device__ __forceinline__ void cpasync16(uint32_t dst, const void* src, int bytes) {
    asm volatile("cp.async.cg.shared.global [%0], [%1], 16, %2;\n"
                 :: "r"(dst), "l"(src), "r"(bytes));
}

__device__ __forceinline__ void mma_bf16(float* c, const uint32_t* a, uint32_t b0, uint32_t b1) {
    asm volatile(
        "mma.sync.aligned.m16n8k16.row.col.f32.bf16.bf16.f32 "
        "{%0,%1,%2,%3},{%4,%5,%6,%7},{%8,%9},{%0,%1,%2,%3};"
        : "+f"(c[0]), "+f"(c[1]), "+f"(c[2]), "+f"(c[3])
        : "r"(a[0]), "r"(a[1]), "r"(a[2]), "r"(a[3]), "r"(b0), "r"(b1));
}

// One R9-style GEMM over rows [row0,row0+128) x cols [col0, col0+2*NTC*8).
// EPI 0: relu(acc+bias) -> bf16 Cv. EPI 1: bn(relu(acc+bias)) -> OUT_BF16 sel.
template <int K, int NTC, int EPI, bool OUT_BF16>
__device__ __forceinline__ void gemm_pass(
    const __nv_bfloat16* __restrict__ A, const __nv_bfloat16* __restrict__ B,
    const float* __restrict__ bias,
    const float* __restrict__ gamma, const float* __restrict__ beta,
    const float* __restrict__ mean, const float* __restrict__ var,
    void* __restrict__ Cv, int M, int col0, char* smc) {
    uint32_t smbase = s2u(smc);
    int tid = threadIdx.x;
    int lane = tid & 31, wid = tid >> 5;
    int warp_m = wid & 3, warp_n = wid >> 2;  // 4x2; warp tile 32 x NTC*8
    int row0 = blockIdx.x * 128;
    int g = lane >> 2, t4 = lane & 3;

    float acc[2][NTC][4];
#pragma unroll
    for (int mt = 0; mt < 2; mt++)
#pragma unroll
        for (int nt = 0; nt < NTC; nt++)
#pragma unroll
            for (int i = 0; i < 4; i++) acc[mt][nt][i] = 0.f;

    int la_m = tid >> 1, la_k = (tid & 1) * 16;
    int ar = row0 + la_m;
    const __nv_bfloat16* aRow = A + (size_t)(ar < M ? ar : 0) * K;
    int lb_r = tid >> 4, lb_c = (tid & 15) * 8;
    bool bcol_ok = (col0 + lb_c) < HDIM;

    const int nk = (K + 31) / 32;

    auto load_stage = [&](int kt) {
        int bi_ = kt % 3;
        uint32_t adst = smbase + (uint32_t)(bi_ * 5120 + la_m * 40 + la_k) * 2;
        int ka0 = kt * 32 + la_k;
        int ab0 = (ar < M && ka0 < K) ? 16 : 0;
        int ab1 = (ar < M && ka0 + 8 < K) ? 16 : 0;
        cpasync16(adst, aRow + (ab0 ? ka0 : 0), ab0);
        cpasync16(adst + 16, aRow + (ab1 ? ka0 + 8 : 0), ab1);
        uint32_t bdst = smbase + (uint32_t)(15360 + bi_ * 4352 + lb_r * 136 + lb_c) * 2;
        int kb0 = kt * 32 + lb_r;
        int bb0 = (kb0 < K && bcol_ok) ? 16 : 0;
        int bb1 = (kb0 + 16 < K && bcol_ok) ? 16 : 0;
        cpasync16(bdst, B + (size_t)(bb0 ? kb0 : 0) * HDIM + col0 + lb_c, bb0);
        cpasync16(bdst + 16 * 272,
                  B + (size_t)(bb1 ? kb0 + 16 : 0) * HDIM + col0 + lb_c, bb1);
        asm volatile("cp.async.commit_group;\n");
    };

    __syncthreads();  // smem buffers free; prior-pass global STG visible block-wide

    load_stage(0);
    if (nk > 1) load_stage(1);

    for (int kt = 0; kt < nk; kt++) {
        if (kt == nk - 1) {
            asm volatile("cp.async.wait_group 0;\n");
        } else {
            asm volatile("cp.async.wait_group 1;\n");
        }
        __syncthreads();
        if (kt + 2 < nk) load_stage(kt + 2);

        int bi = kt % 3;
        uint32_t abase = smbase + (uint32_t)(bi * 5120) * 2;
        uint32_t bbase = smbase + (uint32_t)(15360 + bi * 4352) * 2;
#pragma unroll
        for (int k16 = 0; k16 < 2; k16++) {
            if (kt * 32 + k16 * 16 >= K) break;
            uint32_t af[2][4];
            int arow_f = warp_m * 32 + (lane & 15);
#pragma unroll
            for (int mt = 0; mt < 2; mt++) {
                uint32_t addr = abase + (uint32_t)((arow_f + mt * 16) * 80 + k16 * 32 +
                                                   (lane >> 4) * 16);
                asm volatile("ldmatrix.sync.aligned.m8n8.x4.shared.b16 {%0,%1,%2,%3}, [%4];"
                             : "=r"(af[mt][0]), "=r"(af[mt][1]), "=r"(af[mt][2]), "=r"(af[mt][3])
                             : "r"(addr));
            }
            uint32_t bf[(NTC + 1) / 2][4];
#pragma unroll
            for (int p = 0; p < NTC / 2; p++) {
                uint32_t addr = bbase + (uint32_t)((k16 * 16 + (lane & 15)) * 272 +
                                                   (warp_n * NTC * 8 + p * 16 + (lane >> 4) * 8) * 2);
                asm volatile("ldmatrix.sync.aligned.m8n8.x4.trans.shared.b16 {%0,%1,%2,%3}, [%4];"
                             : "=r"(bf[p][0]), "=r"(bf[p][1]), "=r"(bf[p][2]), "=r"(bf[p][3])
                             : "r"(addr));
            }
            if (NTC & 1) {
                uint32_t addr = bbase + (uint32_t)((k16 * 16 + (lane & 15)) * 272 +
                                                   (warp_n * NTC * 8 + (NTC / 2) * 16) * 2);
                asm volatile("ldmatrix.sync.aligned.m8n8.x2.trans.shared.b16 {%0,%1}, [%2];"
                             : "=r"(bf[NTC / 2][0]), "=r"(bf[NTC / 2][1])
                             : "r"(addr));
            }
#pragma unroll
            for (int nt = 0; nt < NTC; nt++) {
                uint32_t b0 = bf[nt >> 1][(nt & 1) * 2];
                uint32_t b1 = bf[nt >> 1][(nt & 1) * 2 + 1];
                mma_bf16(acc[0][nt], af[0], b0, b1);
                mma_bf16(acc[1][nt], af[1], b0, b1);
            }
        }
    }

#pragma unroll
    for (int nt = 0; nt < NTC; nt++) {
        int col = col0 + warp_n * NTC * 8 + nt * 8 + 2 * t4;
        if (col >= HDIM) continue;
        float bi0 = bias[col], bi1 = bias[col + 1];
        float s0 = 1.f, s1 = 1.f, o0 = 0.f, o1 = 0.f;
        if (EPI == 1) {
            s0 = rsqrtf(var[col] + BN_EPS) * gamma[col];
            s1 = rsqrtf(var[col + 1] + BN_EPS) * gamma[col + 1];
            o0 = beta[col] - mean[col] * s0;
            o1 = beta[col + 1] - mean[col + 1] * s1;
        }
#pragma unroll
        for (int mt = 0; mt < 2; mt++) {
#pragma unroll
            for (int h = 0; h < 2; h++) {
                int r = row0 + warp_m * 32 + mt * 16 + g + h * 8;
                if (r >= M) continue;
                float v0 = fmaxf(acc[mt][nt][2 * h + 0] + bi0, 0.f);
                float v1 = fmaxf(acc[mt][nt][2 * h + 1] + bi1, 0.f);
                if (EPI == 1) { v0 = v0 * s0 + o0; v1 = v1 * s1 + o1; }
                if (EPI == 0 || OUT_BF16) {
                    *(__nv_bfloat162*)((__nv_bfloat16*)Cv + (size_t)r * HDIM + col) =
                        __floats2bfloat162_rn(v0, v1);
                } else {
                    *(float2*)((float*)Cv + (size_t)r * HDIM + col) = make_float2(v0, v1);
                }
            }
        }
    }
}

// one kernel per GIN layer: T = relu(A@Wa+ba) -> g_tb (global);  C = bn(relu(T@Wb+bb))
template <int K, bool OUT_BF16>
__global__ __launch_bounds__(256) void mlp_kernel(
    const __nv_bfloat16* __restrict__ A,
    const __nv_bfloat16* __restrict__ Wa, const float* __restrict__ ba,
    const __nv_bfloat16* __restrict__ Wb, const float* __restrict__ bbias,
    const float* __restrict__ gamma, const float* __restrict__ beta,
    const float* __restrict__ mean, const float* __restrict__ var,
    __nv_bfloat16* __restrict__ tbuf, void* __restrict__ Cv, int M) {
    extern __shared__ __align__(16) char smc[];
    gemm_pass<K, 8, 0, true>(A, Wa, ba, nullptr, nullptr, nullptr, nullptr,
                             tbuf, M, 0, smc);
    gemm_pass<K, 5, 0, true>(A, Wa, ba, nullptr, nullptr, nullptr, nullptr,
                             tbuf, M, 128, smc);
    gemm_pass<200, 8, 1, OUT_BF16>(tbuf, Wb, bbias, gamma, beta, mean, var,
                                   Cv, M, 0, smc);
    gemm_pass<200, 5, 1, OUT_BF16>(tbuf, Wb, bbias, gamma, beta, mean, var,
                                   Cv, M, 128, smc);
}

// ---------------- fused pooling + FC + log_softmax ----------------
__global__ __launch_bounds__(256) void poolfc_kernel(const int* __restrict__ batch,
                                                     const float* __restrict__ Wfc,
                                                     const float* __restrict__ bfc,
                                                     float* __restrict__ out) {
    int gid = blockIdx.x;
    int f = threadIdx.x;
    __shared__ int sb[2];
    __shared__ float red0[8], red1[8];
    if (f < 2) {
        int tgt = gid + f;
        int lo = 0, hi = N_NODES;
        while (lo < hi) {
            int mid = (lo + hi) >> 1;
            if (batch[mid] < tgt) lo = mid + 1; else hi = mid;
        }
        sb[f] = lo;
    }
    __syncthreads();
    int beg = sb[0], end = sb[1];
    float l0 = 0.f, l1 = 0.f;
    if (f < HDIM) {
        float s = 0.f, m = -INFINITY;
        for (int i = beg; i < end; i++) {
            float v = g_h2[(size_t)i * HDIM + f];
            s += v;
            m = fmaxf(m, v);
        }
        l0 = s * Wfc[f * 2 + 0] + m * Wfc[(HDIM + f) * 2 + 0];
        l1 = s * Wfc[f * 2 + 1] + m * Wfc[(HDIM + f) * 2 + 1];
    }
#pragma unroll
    for (int off = 16; off; off >>= 1) {
        l0 += __shfl_down_sync(0xFFFFFFFFu, l0, off);
        l1 += __shfl_down_sync(0xFFFFFFFFu, l1, off);
    }
    int lane = f & 31, wid = f >> 5;
    if (lane == 0) { red0[wid] = l0; red1[wid] = l1; }
    __syncthreads();
    if (f == 0) {
        float t0 = 0.f, t1 = 0.f;
#pragma unroll
        for (int wi = 0; wi < 8; wi++) { t0 += red0[wi]; t1 += red1[wi]; }
        t0 += bfc[0];
        t1 += bfc[1];
        float m = fmaxf(t0, t1);
        float lse = m + logf(expf(t0 - m) + expf(t1 - m));
        out[gid * 2 + 0] = t0 - lse;
        out[gid * 2 + 1] = t1 - lse;
    }
}

// ---------------- launch ----------------
extern "C" void kernel_launch(void* const* d_in, const int* in_sizes, int n_in,
                              void* d_out, int out_size) {
    const float* x    = (const float*)d_in[0];
    const int*   ei   = (const int*)d_in[1];
    const int*   batch = (const int*)d_in[2];
    const float* eps1 = (const float*)d_in[3];
    const float* W1a  = (const float*)d_in[4];
    const float* b1a  = (const float*)d_in[5];
    const float* W1b  = (const float*)d_in[6];
    const float* b1b  = (const float*)d_in[7];
    const float* bn1g = (const float*)d_in[8];
    const float* bn1b = (const float*)d_in[9];
    const float* bn1m = (const float*)d_in[10];
    const float* bn1v = (const float*)d_in[11];
    const float* eps2 = (const float*)d_in[12];
    const float* W2a  = (const float*)d_in[13];
    const float* b2a  = (const float*)d_in[14];
    const float* W2b  = (const float*)d_in[15];
    const float* b2b  = (const float*)d_in[16];
    const float* bn2g = (const float*)d_in[17];
    const float* bn2b = (const float*)d_in[18];
    const float* bn2m = (const float*)d_in[19];
    const float* bn2v = (const float*)d_in[20];
    const float* Wfc  = (const float*)d_in[21];
    const float* bfc  = (const float*)d_in[22];
    float* out = (float*)d_out;

    const int* src = ei;
    const int* dst = ei + N_EDGES;

    __nv_bfloat16 *xb, *hin1, *tb, *h1, *hin2, *w1a, *w1b, *w2a, *w2b;
    float* h2;
    cudaGetSymbolAddress((void**)&xb,   g_xb);
    cudaGetSymbolAddress((void**)&hin1, g_hin1);
    cudaGetSymbolAddress((void**)&tb,   g_tb);
    cudaGetSymbolAddress((void**)&h1,   g_h1);
    cudaGetSymbolAddress((void**)&hin2, g_hin2);
    cudaGetSymbolAddress((void**)&h2,   g_h2);
    cudaGetSymbolAddress((void**)&w1a,  g_w1a);
    cudaGetSymbolAddress((void**)&w1b,  g_w1b);
    cudaGetSymbolAddress((void**)&w2a,  g_w2a);
    cudaGetSymbolAddress((void**)&w2b,  g_w2b);

    cudaFuncSetAttribute(mlp_kernel<64, true>,
                         cudaFuncAttributeMaxDynamicSharedMemorySize, GEMM_SMEM_BYTES);
    cudaFuncSetAttribute(mlp_kernel<200, false>,
                         cudaFuncAttributeMaxDynamicSharedMemorySize, GEMM_SMEM_BYTES);

    const int TPB = 256;
    int nbEdges8 = (N_EDGES / 8 + TPB - 1) / TPB;
    int nbNodes = (N_NODES + TPB - 1) / TPB;
    int nbWarpNodes = (N_NODES * 32 + TPB - 1) / TPB;
    int mlp_grid = (N_NODES + 127) / 128;  // 782

    // CSR build + conversions
    convhist_kernel<<<CONV_BLOCKS + HIST_BLOCKS, TPB>>>(x, W1a, W1b, W2a, W2b, (const int4*)dst);
    scan_block_kernel<<<NB_SCAN, 1024>>>();
    scan_apply_kernel<<<nbNodes, TPB>>>();
    fill_kernel<<<nbEdges8, TPB>>>((const int4*)src, (const int4*)dst);

    // Layer 1
    agg64_kernel<<<nbWarpNodes, TPB>>>(xb, eps1, hin1);
    mlp_kernel<64, true><<<mlp_grid, 256, GEMM_SMEM_BYTES>>>(
        hin1, w1a, b1a, w1b, b1b, bn1g, bn1b, bn1m, bn1v, tb, h1, N_NODES);

    // Layer 2
    agg200_kernel<<<nbWarpNodes, TPB>>>(h1, eps2, hin2);
    mlp_kernel<200, false><<<mlp_grid, 256, GEMM_SMEM_BYTES>>>(
        hin2, w2a, b2a, w2b, b2b, bn2g, bn2b, bn2m, bn2v, tb, h2, N_NODES);

    // fused pooling + FC + log_softmax
    poolfc_kernel<<<N_GRAPHS, 256>>>(batch, Wfc, bfc, out);
}

// round 14
// speedup vs baseline: 1.1478x; 1.1039x over previous
#include <cuda_runtime.h>
#include <cuda_bf16.h>
#include <math.h>
#include <stdint.h>

#define N_NODES 100000
#define N_EDGES 1600000
#define F_IN 64
#define HDIM 200
#define N_GRAPHS 512
#define BN_EPS 1e-5f
#define NB_SCAN 98

#define CONV_TOTAL (N_NODES * F_IN + F_IN * HDIM + 3 * HDIM * HDIM)
#define CONV_BLOCKS ((CONV_TOTAL + 255) / 256)
#define HIST_BLOCKS ((N_EDGES / 8 + 255) / 256)

// fused-MLP smem layout (bytes):
//   Ts @ 0      : 128 rows x 216 bf16, stride 432 B (%128==48 -> conflict-free ldmatrix)
//   As @ 55296  : 3 stages x 128x40 bf16 (10240 B each)   [stage2 reuses as B buffers]
//   Bs @ 86016  : 3 stages x 32x136 bf16 (8704 B each)
#define TS_STRIDE 432
#define TS_BYTES  55296
#define AS_OFF    55296
#define AS_STAGE  10240
#define BS_OFF    86016
#define BS_STAGE  8704
#define MLP_SMEM  (BS_OFF + 3 * BS_STAGE)   // 112128

// ---------------- scratch (device globals; no allocation allowed) ----------------
__device__ int g_deg[N_NODES];        // zero-init at load; scan_block re-zeros each call
__device__ int g_excl[N_NODES];
__device__ int g_bsum[128];
__device__ int g_rowptr[N_NODES + 1];
__device__ __align__(16) int g_rank[N_EDGES];
__device__ int g_csrsrc[N_EDGES];

__device__ __align__(16) __nv_bfloat16 g_xb[(size_t)N_NODES * F_IN];
__device__ __align__(16) __nv_bfloat16 g_hin1[(size_t)N_NODES * F_IN];
__device__ __align__(16) __nv_bfloat16 g_h1[(size_t)N_NODES * HDIM];
__device__ __align__(16) __nv_bfloat16 g_hin2[(size_t)N_NODES * HDIM];
__device__ __align__(16) float g_h2[(size_t)N_NODES * HDIM];
__device__ __align__(16) __nv_bfloat16 g_w1a[F_IN * HDIM];
__device__ __align__(16) __nv_bfloat16 g_w1b[HDIM * HDIM];
__device__ __align__(16) __nv_bfloat16 g_w2a[HDIM * HDIM];
__device__ __align__(16) __nv_bfloat16 g_w2b[HDIM * HDIM];

// ---------------- fused conversion + edge histogram ----------
__global__ void convhist_kernel(const float* __restrict__ x,
                                const float* __restrict__ W1a, const float* __restrict__ W1b,
                                const float* __restrict__ W2a, const float* __restrict__ W2b,
                                const int4* __restrict__ dst4) {
    if (blockIdx.x < CONV_BLOCKS) {
        int i = blockIdx.x * 256 + threadIdx.x;
        const int XN = N_NODES * F_IN;
        const int S1 = XN + F_IN * HDIM;
        const int S2 = S1 + HDIM * HDIM;
        const int S3 = S2 + HDIM * HDIM;
        const int S4 = S3 + HDIM * HDIM;
        if (i < XN)       g_xb[i]       = __float2bfloat16(x[i]);
        else if (i < S1)  g_w1a[i - XN] = __float2bfloat16(W1a[i - XN]);
        else if (i < S2)  g_w1b[i - S1] = __float2bfloat16(W1b[i - S1]);
        else if (i < S3)  g_w2a[i - S2] = __float2bfloat16(W2a[i - S2]);
        else if (i < S4)  g_w2b[i - S3] = __float2bfloat16(W2b[i - S3]);
    } else {
        int i = (blockIdx.x - CONV_BLOCKS) * 256 + threadIdx.x;
        if (i < N_EDGES / 8) {
            int4 d0 = __ldg(dst4 + 2 * i);
            int4 d1 = __ldg(dst4 + 2 * i + 1);
            int4 r0, r1;
            r0.x = atomicAdd(&g_deg[d0.x], 1);
            r0.y = atomicAdd(&g_deg[d0.y], 1);
            r0.z = atomicAdd(&g_deg[d0.z], 1);
            r0.w = atomicAdd(&g_deg[d0.w], 1);
            r1.x = atomicAdd(&g_deg[d1.x], 1);
            r1.y = atomicAdd(&g_deg[d1.y], 1);
            r1.z = atomicAdd(&g_deg[d1.z], 1);
            r1.w = atomicAdd(&g_deg[d1.w], 1);
            ((int4*)g_rank)[2 * i] = r0;
            ((int4*)g_rank)[2 * i + 1] = r1;
        }
    }
}

// ---------------- CSR scan ----------------
__global__ void scan_block_kernel() {
    __shared__ int ws[32];
    int i = blockIdx.x * 1024 + threadIdx.x;
    int v = 0;
    if (i < N_NODES) {
        v = g_deg[i];
        g_deg[i] = 0;
    }
    int lane = threadIdx.x & 31, wid = threadIdx.x >> 5;
    int s = v;
#pragma unroll
    for (int off = 1; off < 32; off <<= 1) {
        int n = __shfl_up_sync(0xFFFFFFFFu, s, off);
        if (lane >= off) s += n;
    }
    if (lane == 31) ws[wid] = s;
    __syncthreads();
    if (wid == 0) {
        int t = ws[lane];
#pragma unroll
        for (int off = 1; off < 32; off <<= 1) {
            int n = __shfl_up_sync(0xFFFFFFFFu, t, off);
            if (lane >= off) t += n;
        }
        ws[lane] = t;
    }
    __syncthreads();
    int pre = (wid > 0) ? ws[wid - 1] : 0;
    if (i < N_NODES) g_excl[i] = pre + s - v;
    if (threadIdx.x == 1023) g_bsum[blockIdx.x] = ws[31];
}

__global__ void scan_apply_kernel() {
    __shared__ int pre[NB_SCAN];
    if (threadIdx.x == 0) {
        int run = 0;
#pragma unroll
        for (int b = 0; b < NB_SCAN; b++) {
            int t = g_bsum[b];
            pre[b] = run;
            run += t;
        }
    }
    __syncthreads();
    int i = blockIdx.x * blockDim.x + threadIdx.x;
    if (i < N_NODES) g_rowptr[i] = g_excl[i] + pre[i >> 10];
    if (i == 0) g_rowptr[N_NODES] = N_EDGES;
}

__global__ void fill_kernel(const int4* __restrict__ src4, const int4* __restrict__ dst4) {
    int i = blockIdx.x * blockDim.x + threadIdx.x;
    if (i < N_EDGES / 8) {
        int4 s0 = __ldg(src4 + 2 * i);
        int4 d0 = __ldg(dst4 + 2 * i);
        int4 r0 = ((const int4*)g_rank)[2 * i];
        int4 s1 = __ldg(src4 + 2 * i + 1);
        int4 d1 = __ldg(dst4 + 2 * i + 1);
        int4 r1 = ((const int4*)g_rank)[2 * i + 1];
        g_csrsrc[g_rowptr[d0.x] + r0.x] = s0.x;
        g_csrsrc[g_rowptr[d0.y] + r0.y] = s0.y;
        g_csrsrc[g_rowptr[d0.z] + r0.z] = s0.z;
        g_csrsrc[g_rowptr[d0.w] + r0.w] = s0.w;
        g_csrsrc[g_rowptr[d1.x] + r1.x] = s1.x;
        g_csrsrc[g_rowptr[d1.y] + r1.y] = s1.y;
        g_csrsrc[g_rowptr[d1.z] + r1.z] = s1.z;
        g_csrsrc[g_rowptr[d1.w] + r1.w] = s1.w;
    }
}

// ---------------- GIN aggregation (bf16 in, fp32 accumulate, bf16 out) ----------
__global__ void agg64_kernel(const __nv_bfloat16* __restrict__ X, const float* __restrict__ epsp,
                             __nv_bfloat16* __restrict__ out) {
    int w = (blockIdx.x * blockDim.x + threadIdx.x) >> 5;
    int lane = threadIdx.x & 31;
    if (w >= N_NODES) return;
    float2 a0 = {0.f, 0.f}, a1 = {0.f, 0.f}, a2 = {0.f, 0.f}, a3 = {0.f, 0.f};
    int beg = g_rowptr[w], end = g_rowptr[w + 1];
    int e = beg;
    for (; e + 4 <= end; e += 4) {
        int s0 = g_csrsrc[e], s1 = g_csrsrc[e + 1], s2 = g_csrsrc[e + 2], s3 = g_csrsrc[e + 3];
        float2 f0 = __bfloat1622float2(__ldg((const __nv_bfloat162*)(X + (size_t)s0 * F_IN) + lane));
        float2 f1 = __bfloat1622float2(__ldg((const __nv_bfloat162*)(X + (size_t)s1 * F_IN) + lane));
        float2 f2 = __bfloat1622float2(__ldg((const __nv_bfloat162*)(X + (size_t)s2 * F_IN) + lane));
        float2 f3 = __bfloat1622float2(__ldg((const __nv_bfloat162*)(X + (size_t)s3 * F_IN) + lane));
        a0.x += f0.x; a0.y += f0.y;
        a1.x += f1.x; a1.y += f1.y;
        a2.x += f2.x; a2.y += f2.y;
        a3.x += f3.x; a3.y += f3.y;
    }
    for (; e < end; e++) {
        int s = g_csrsrc[e];
        float2 f = __bfloat1622float2(__ldg((const __nv_bfloat162*)(X + (size_t)s * F_IN) + lane));
        a0.x += f.x; a0.y += f.y;
    }
    float2 acc = {a0.x + a1.x + a2.x + a3.x, a0.y + a1.y + a2.y + a3.y};
    float ep = 1.f + *epsp;
    float2 xi = __bfloat1622float2(*((const __nv_bfloat162*)(X + (size_t)w * F_IN) + lane));
    *(((__nv_bfloat162*)(out + (size_t)w * F_IN)) + lane) =
        __floats2bfloat162_rn(ep * xi.x + acc.x, ep * xi.y + acc.y);
}

__device__ __forceinline__ void add8(float* a, uint4 v) {
    __nv_bfloat162 p0 = *(__nv_bfloat162*)&v.x;
    __nv_bfloat162 p1 = *(__nv_bfloat162*)&v.y;
    __nv_bfloat162 p2 = *(__nv_bfloat162*)&v.z;
    __nv_bfloat162 p3 = *(__nv_bfloat162*)&v.w;
    float2 f0 = __bfloat1622float2(p0), f1 = __bfloat1622float2(p1);
    float2 f2 = __bfloat1622float2(p2), f3 = __bfloat1622float2(p3);
    a[0] += f0.x; a[1] += f0.y; a[2] += f1.x; a[3] += f1.y;
    a[4] += f2.x; a[5] += f2.y; a[6] += f3.x; a[7] += f3.y;
}

__global__ void agg200_kernel(const __nv_bfloat16* __restrict__ X, const float* __restrict__ epsp,
                              __nv_bfloat16* __restrict__ out) {
    int w = (blockIdx.x * blockDim.x + threadIdx.x) >> 5;
    int lane = threadIdx.x & 31;
    if (w >= N_NODES) return;
    bool act = lane < 25;
    float a[8] = {0.f, 0.f, 0.f, 0.f, 0.f, 0.f, 0.f, 0.f};
    int beg = g_rowptr[w], end = g_rowptr[w + 1];
    int e = beg;
    for (; e + 4 <= end; e += 4) {
        int s0 = g_csrsrc[e], s1 = g_csrsrc[e + 1], s2 = g_csrsrc[e + 2], s3 = g_csrsrc[e + 3];
        if (act) {
            uint4 v0 = __ldg((const uint4*)(X + (size_t)s0 * HDIM) + lane);
            uint4 v1 = __ldg((const uint4*)(X + (size_t)s1 * HDIM) + lane);
            uint4 v2 = __ldg((const uint4*)(X + (size_t)s2 * HDIM) + lane);
            uint4 v3 = __ldg((const uint4*)(X + (size_t)s3 * HDIM) + lane);
            add8(a, v0);
            add8(a, v1);
            add8(a, v2);
            add8(a, v3);
        }
    }
    for (; e < end; e++) {
        int s = g_csrsrc[e];
        if (act) add8(a, __ldg((const uint4*)(X + (size_t)s * HDIM) + lane));
    }
    if (!act) return;
    float ep = 1.f + *epsp;
    float xs[8] = {0.f, 0.f, 0.f, 0.f, 0.f, 0.f, 0.f, 0.f};
    add8(xs, *((const uint4*)(X + (size_t)w * HDIM) + lane));
    float r[8];
#pragma unroll
    for (int j = 0; j < 8; j++) r[j] = ep * xs[j] + a[j];
    uint4 u;
    __nv_bfloat162 p0 = __floats2bfloat162_rn(r[0], r[1]);
    __nv_bfloat162 p1 = __floats2bfloat162_rn(r[2], r[3]);
    __nv_bfloat162 p2 = __floats2bfloat162_rn(r[4], r[5]);
    __nv_bfloat162 p3 = __floats2bfloat162_rn(r[6], r[7]);
    u.x = *(uint32_t*)&p0; u.y = *(uint32_t*)&p1;
    u.z = *(uint32_t*)&p2; u.w = *(uint32_t*)&p3;
    *((uint4*)(out + (size_t)w * HDIM) + lane) = u;
}

// ---------------- fused MLP helpers ----------------
__device__ __forceinline__ uint32_t s2u(const void* p) {
    return (uint32_t)__cvta_generic_to_shared(p);
}

__device__ __forceinline__ void cpasync16(uint32_t dst, const void* src, int bytes) {
    asm volatile("cp.async.cg.shared.global [%0], [%1], 16, %2;\n"
                 :: "r"(dst), "l"(src), "r"(bytes));
}

__device__ __forceinline__ void mma_bf16(float* c, const uint32_t* a, uint32_t b0, uint32_t b1) {
    asm volatile(
        "mma.sync.aligned.m16n8k16.row.col.f32.bf16.bf16.f32 "
        "{%0,%1,%2,%3},{%4,%5,%6,%7},{%8,%9},{%0,%1,%2,%3};"
        : "+f"(c[0]), "+f"(c[1]), "+f"(c[2]), "+f"(c[3])
        : "r"(a[0]), "r"(a[1]), "r"(a[2]), "r"(a[3]), "r"(b0), "r"(b1));
}

// stage 1: acc = A@Wa over [row0..row0+128) x [col0..col0+2*NTC*8); Ts <- relu(acc+ba)
template <int K, int NTC>
__device__ __forceinline__ void stage1_pass(
    const __nv_bfloat16* __restrict__ A, const __nv_bfloat16* __restrict__ Wa,
    const float* __restrict__ ba, int M, int col0, char* smc) {
    uint32_t smbase = s2u(smc);
    int tid = threadIdx.x;
    int lane = tid & 31, wid = tid >> 5;
    int warp_m = wid & 3, warp_n = wid >> 2;
    int row0 = blockIdx.x * 128;
    int g = lane >> 2, t4 = lane & 3;

    float acc[2][NTC][4];
#pragma unroll
    for (int mt = 0; mt < 2; mt++)
#pragma unroll
        for (int nt = 0; nt < NTC; nt++)
#pragma unroll
            for (int i = 0; i < 4; i++) acc[mt][nt][i] = 0.f;

    int la_m = tid >> 1, la_k = (tid & 1) * 16;
    int ar = row0 + la_m;
    const __nv_bfloat16* aRow = A + (size_t)(ar < M ? ar : 0) * K;
    int lb_r = tid >> 4, lb_c = (tid & 15) * 8;
    bool bcol_ok = (col0 + lb_c) < HDIM;

    const int nk = (K + 31) / 32;

    auto load_stage = [&](int kt) {
        int bi_ = kt % 3;
        uint32_t adst = smbase + AS_OFF + bi_ * AS_STAGE + (uint32_t)(la_m * 40 + la_k) * 2;
        int ka0 = kt * 32 + la_k;
        int ab0 = (ar < M && ka0 < K) ? 16 : 0;
        int ab1 = (ar < M && ka0 + 8 < K) ? 16 : 0;
        cpasync16(adst, aRow + (ab0 ? ka0 : 0), ab0);
        cpasync16(adst + 16, aRow + (ab1 ? ka0 + 8 : 0), ab1);
        uint32_t bdst = smbase + BS_OFF + bi_ * BS_STAGE + (uint32_t)(lb_r * 136 + lb_c) * 2;
        int kb0 = kt * 32 + lb_r;
        int bb0 = (kb0 < K && bcol_ok) ? 16 : 0;
        int bb1 = (kb0 + 16 < K && bcol_ok) ? 16 : 0;
        cpasync16(bdst, Wa + (size_t)(bb0 ? kb0 : 0) * HDIM + col0 + lb_c, bb0);
        cpasync16(bdst + 16 * 272,
                  Wa + (size_t)(bb1 ? kb0 + 16 : 0) * HDIM + col0 + lb_c, bb1);
        asm volatile("cp.async.commit_group;\n");
    };

    __syncthreads();

    load_stage(0);
    if (nk > 1) load_stage(1);

    for (int kt = 0; kt < nk; kt++) {
        if (kt == nk - 1) {
            asm volatile("cp.async.wait_group 0;\n");
        } else {
            asm volatile("cp.async.wait_group 1;\n");
        }
        __syncthreads();
        if (kt + 2 < nk) load_stage(kt + 2);

        int bi = kt % 3;
        uint32_t abase = smbase + AS_OFF + bi * AS_STAGE;
        uint32_t bbase = smbase + BS_OFF + bi * BS_STAGE;
#pragma unroll
        for (int k16 = 0; k16 < 2; k16++) {
            if (kt * 32 + k16 * 16 >= K) break;
            uint32_t af[2][4];
            int arow_f = warp_m * 32 + (lane & 15);
#pragma unroll
            for (int mt = 0; mt < 2; mt++) {
                uint32_t addr = abase + (uint32_t)((arow_f + mt * 16) * 80 + k16 * 32 +
                                                   (lane >> 4) * 16);
                asm volatile("ldmatrix.sync.aligned.m8n8.x4.shared.b16 {%0,%1,%2,%3}, [%4];"
                             : "=r"(af[mt][0]), "=r"(af[mt][1]), "=r"(af[mt][2]), "=r"(af[mt][3])
                             : "r"(addr));
            }
            uint32_t bf[(NTC + 1) / 2][4];
#pragma unroll
            for (int p = 0; p < NTC / 2; p++) {
                uint32_t addr = bbase + (uint32_t)((k16 * 16 + (lane & 15)) * 272 +
                                                   (warp_n * NTC * 8 + p * 16 + (lane >> 4) * 8) * 2);
                asm volatile("ldmatrix.sync.aligned.m8n8.x4.trans.shared.b16 {%0,%1,%2,%3}, [%4];"
                             : "=r"(bf[p][0]), "=r"(bf[p][1]), "=r"(bf[p][2]), "=r"(bf[p][3])
                             : "r"(addr));
            }
            if (NTC & 1) {
                uint32_t addr = bbase + (uint32_t)((k16 * 16 + (lane & 15)) * 272 +
                                                   (warp_n * NTC * 8 + (NTC / 2) * 16) * 2);
                asm volatile("ldmatrix.sync.aligned.m8n8.x2.trans.shared.b16 {%0,%1}, [%2];"
                             : "=r"(bf[NTC / 2][0]), "=r"(bf[NTC / 2][1])
                             : "r"(addr));
            }
#pragma unroll
            for (int nt = 0; nt < NTC; nt++) {
                uint32_t b0 = bf[nt >> 1][(nt & 1) * 2];
                uint32_t b1 = bf[nt >> 1][(nt & 1) * 2 + 1];
                mma_bf16(acc[0][nt], af[0], b0, b1);
                mma_bf16(acc[1][nt], af[1], b0, b1);
            }
        }
    }

    // epilogue: relu(acc + ba) -> Ts (smem, bf16; identical rounding to tb path)
#pragma unroll
    for (int nt = 0; nt < NTC; nt++) {
        int col = col0 + warp_n * NTC * 8 + nt * 8 + 2 * t4;
        if (col >= HDIM) continue;
        float b0 = ba[col], b1 = ba[col + 1];
#pragma unroll
        for (int mt = 0; mt < 2; mt++)
#pragma unroll
            for (int h = 0; h < 2; h++) {
                int rl = warp_m * 32 + mt * 16 + g + h * 8;
                float v0 = fmaxf(acc[mt][nt][2 * h + 0] + b0, 0.f);
                float v1 = fmaxf(acc[mt][nt][2 * h + 1] + b1, 0.f);
                *(__nv_bfloat162*)(smc + rl * TS_STRIDE + col * 2) =
                    __floats2bfloat162_rn(v0, v1);
            }
    }
}

// stage 2: C = bn(relu(Ts@Wb+bb)); A-fragments ldmatrix'd directly from Ts
template <int NTC, bool OUT_BF16>
__device__ __forceinline__ void stage2_pass(
    const __nv_bfloat16* __restrict__ Wb, const float* __restrict__ bb,
    const float* __restrict__ gamma, const float* __restrict__ beta,
    const float* __restrict__ mean, const float* __restrict__ var,
    void* __restrict__ Cv, int M, int col0, char* smc) {
    uint32_t smbase = s2u(smc);
    int tid = threadIdx.x;
    int lane = tid & 31, wid = tid >> 5;
    int warp_m = wid & 3, warp_n = wid >> 2;
    int row0 = blockIdx.x * 128;
    int g = lane >> 2, t4 = lane & 3;

    float acc[2][NTC][4];
#pragma unroll
    for (int mt = 0; mt < 2; mt++)
#pragma unroll
        for (int nt = 0; nt < NTC; nt++)
#pragma unroll
            for (int i = 0; i < 4; i++) acc[mt][nt][i] = 0.f;

    int lb_r = tid >> 4, lb_c = (tid & 15) * 8;
    bool bcol_ok = (col0 + lb_c) < HDIM;

    const int nk = 7;  // (200+31)/32

    auto load_stage = [&](int kt) {
        int bi_ = kt % 3;
        uint32_t bdst = smbase + AS_OFF + bi_ * BS_STAGE + (uint32_t)(lb_r * 136 + lb_c) * 2;
        int kb0 = kt * 32 + lb_r;
        int bb0 = (kb0 < HDIM && bcol_ok) ? 16 : 0;
        int bb1 = (kb0 + 16 < HDIM && bcol_ok) ? 16 : 0;
        cpasync16(bdst, Wb + (size_t)(bb0 ? kb0 : 0) * HDIM + col0 + lb_c, bb0);
        cpasync16(bdst + 16 * 272,
                  Wb + (size_t)(bb1 ? kb0 + 16 : 0) * HDIM + col0 + lb_c, bb1);
        asm volatile("cp.async.commit_group;\n");
    };

    __syncthreads();  // Ts complete / B buffers free

    load_stage(0);
    load_stage(1);

    for (int kt = 0; kt < nk; kt++) {
        if (kt == nk - 1) {
            asm volatile("cp.async.wait_group 0;\n");
        } else {
            asm volatile("cp.async.wait_group 1;\n");
        }
        __syncthreads();
        if (kt + 2 < nk) load_stage(kt + 2);

        int bi = kt % 3;
        uint32_t bbase = smbase + AS_OFF + bi * BS_STAGE;
#pragma unroll
        for (int k16 = 0; k16 < 2; k16++) {
            int kbase = kt * 32 + k16 * 16;
            if (kbase >= HDIM) break;   // k 200..207 of last chunk covered inside k192 tile
            uint32_t af[2][4];
            int arow_f = warp_m * 32 + (lane & 15);
#pragma unroll
            for (int mt = 0; mt < 2; mt++) {
                uint32_t addr = smbase + (uint32_t)((arow_f + mt * 16) * TS_STRIDE +
                                                    kbase * 2 + (lane >> 4) * 16);
                asm volatile("ldmatrix.sync.aligned.m8n8.x4.shared.b16 {%0,%1,%2,%3}, [%4];"
                             : "=r"(af[mt][0]), "=r"(af[mt][1]), "=r"(af[mt][2]), "=r"(af[mt][3])
                             : "r"(addr));
            }
            uint32_t bf[(NTC + 1) / 2][4];
#pragma unroll
            for (int p = 0; p < NTC / 2; p++) {
                uint32_t addr = bbase + (uint32_t)((k16 * 16 + (lane & 15)) * 272 +
                                                   (warp_n * NTC * 8 + p * 16 + (lane >> 4) * 8) * 2);
                asm volatile("ldmatrix.sync.aligned.m8n8.x4.trans.shared.b16 {%0,%1,%2,%3}, [%4];"
                             : "=r"(bf[p][0]), "=r"(bf[p][1]), "=r"(bf[p][2]), "=r"(bf[p][3])
                             : "r"(addr));
            }
            if (NTC & 1) {
                uint32_t addr = bbase + (uint32_t)((k16 * 16 + (lane & 15)) * 272 +
                                                   (warp_n * NTC * 8 + (NTC / 2) * 16) * 2);
                asm volatile("ldmatrix.sync.aligned.m8n8.x2.trans.shared.b16 {%0,%1}, [%2];"
                             : "=r"(bf[NTC / 2][0]), "=r"(bf[NTC / 2][1])
                             : "r"(addr));
            }
#pragma unroll
            for (int nt = 0; nt < NTC; nt++) {
                uint32_t b0 = bf[nt >> 1][(nt & 1) * 2];
                uint32_t b1 = bf[nt >> 1][(nt & 1) * 2 + 1];
                mma_bf16(acc[0][nt], af[0], b0, b1);
                mma_bf16(acc[1][nt], af[1], b0, b1);
            }
        }
    }

#pragma unroll
    for (int nt = 0; nt < NTC; nt++) {
        int col = col0 + warp_n * NTC * 8 + nt * 8 + 2 * t4;
        if (col >= HDIM) continue;
        float bi0 = bb[col], bi1 = bb[col + 1];
        float s0 = rsqrtf(var[col] + BN_EPS) * gamma[col];
        float s1 = rsqrtf(var[col + 1] + BN_EPS) * gamma[col + 1];
        float o0 = beta[col] - mean[col] * s0;
        float o1 = beta[col + 1] - mean[col + 1] * s1;
#pragma unroll
        for (int mt = 0; mt < 2; mt++) {
#pragma unroll
            for (int h = 0; h < 2; h++) {
                int r = row0 + warp_m * 32 + mt * 16 + g + h * 8;
                if (r >= M) continue;
                float v0 = fmaxf(acc[mt][nt][2 * h + 0] + bi0, 0.f) * s0 + o0;
                float v1 = fmaxf(acc[mt][nt][2 * h + 1] + bi1, 0.f) * s1 + o1;
                if (OUT_BF16) {
                    *(__nv_bfloat162*)((__nv_bfloat16*)Cv + (size_t)r * HDIM + col) =
                        __floats2bfloat162_rn(v0, v1);
                } else {
                    *(float2*)((float*)Cv + (size_t)r * HDIM + col) = make_float2(v0, v1);
                }
            }
        }
    }
}

// one kernel per GIN layer: Ts = relu(A@Wa+ba) in smem; C = bn(relu(Ts@Wb+bb))
template <int K, bool OUT_BF16>
__global__ __launch_bounds__(256) void mlp_kernel(
    const __nv_bfloat16* __restrict__ A,
    const __nv_bfloat16* __restrict__ Wa, const float* __restrict__ ba,
    const __nv_bfloat16* __restrict__ Wb, const float* __restrict__ bbias,
    const float* __restrict__ gamma, const float* __restrict__ beta,
    const float* __restrict__ mean, const float* __restrict__ var,
    void* __restrict__ Cv, int M) {
    extern __shared__ __align__(16) char smc[];
    // zero Ts padding cols 200..207 (prevents NaN/Inf garbage entering k192 MMA tile)
    if (threadIdx.x < 128)
        *(uint4*)(smc + threadIdx.x * TS_STRIDE + 400) = make_uint4(0, 0, 0, 0);

    stage1_pass<K, 8>(A, Wa, ba, M, 0, smc);
    stage1_pass<K, 5>(A, Wa, ba, M, 128, smc);
    stage2_pass<8, OUT_BF16>(Wb, bbias, gamma, beta, mean, var, Cv, M, 0, smc);
    stage2_pass<5, OUT_BF16>(Wb, bbias, gamma, beta, mean, var, Cv, M, 128, smc);
}

// ---------------- fused pooling + FC + log_softmax ----------------
__global__ __launch_bounds__(256) void poolfc_kernel(const int* __restrict__ batch,
                                                     const float* __restrict__ Wfc,
                                                     const float* __restrict__ bfc,
                                                     float* __restrict__ out) {
    int gid = blockIdx.x;
    int f = threadIdx.x;
    __shared__ int sb[2];
    __shared__ float red0[8], red1[8];
    if (f < 2) {
        int tgt = gid + f;
        int lo = 0, hi = N_NODES;
        while (lo < hi) {
            int mid = (lo + hi) >> 1;
            if (batch[mid] < tgt) lo = mid + 1; else hi = mid;
        }
        sb[f] = lo;
    }
    __syncthreads();
    int beg = sb[0], end = sb[1];
    float l0 = 0.f, l1 = 0.f;
    if (f < HDIM) {
        float s = 0.f, m = -INFINITY;
        for (int i = beg; i < end; i++) {
            float v = g_h2[(size_t)i * HDIM + f];
            s += v;
            m = fmaxf(m, v);
        }
        l0 = s * Wfc[f * 2 + 0] + m * Wfc[(HDIM + f) * 2 + 0];
        l1 = s * Wfc[f * 2 + 1] + m * Wfc[(HDIM + f) * 2 + 1];
    }
#pragma unroll
    for (int off = 16; off; off >>= 1) {
        l0 += __shfl_down_sync(0xFFFFFFFFu, l0, off);
        l1 += __shfl_down_sync(0xFFFFFFFFu, l1, off);
    }
    int lane = f & 31, wid = f >> 5;
    if (lane == 0) { red0[wid] = l0; red1[wid] = l1; }
    __syncthreads();
    if (f == 0) {
        float t0 = 0.f, t1 = 0.f;
#pragma unroll
        for (int wi = 0; wi < 8; wi++) { t0 += red0[wi]; t1 += red1[wi]; }
        t0 += bfc[0];
        t1 += bfc[1];
        float m = fmaxf(t0, t1);
        float lse = m + logf(expf(t0 - m) + expf(t1 - m));
        out[gid * 2 + 0] = t0 - lse;
        out[gid * 2 + 1] = t1 - lse;
    }
}

// ---------------- launch ----------------
extern "C" void kernel_launch(void* const* d_in, const int* in_sizes, int n_in,
                              void* d_out, int out_size) {
    const float* x    = (const float*)d_in[0];
    const int*   ei   = (const int*)d_in[1];
    const int*   batch = (const int*)d_in[2];
    const float* eps1 = (const float*)d_in[3];
    const float* W1a  = (const float*)d_in[4];
    const float* b1a  = (const float*)d_in[5];
    const float* W1b  = (const float*)d_in[6];
    const float* b1b  = (const float*)d_in[7];
    const float* bn1g = (const float*)d_in[8];
    const float* bn1b = (const float*)d_in[9];
    const float* bn1m = (const float*)d_in[10];
    const float* bn1v = (const float*)d_in[11];
    const float* eps2 = (const float*)d_in[12];
    const float* W2a  = (const float*)d_in[13];
    const float* b2a  = (const float*)d_in[14];
    const float* W2b  = (const float*)d_in[15];
    const float* b2b  = (const float*)d_in[16];
    const float* bn2g = (const float*)d_in[17];
    const float* bn2b = (const float*)d_in[18];
    const float* bn2m = (const float*)d_in[19];
    const float* bn2v = (const float*)d_in[20];
    const float* Wfc  = (const float*)d_in[21];
    const float* bfc  = (const float*)d_in[22];
    float* out = (float*)d_out;

    const int* src = ei;
    const int* dst = ei + N_EDGES;

    __nv_bfloat16 *xb, *hin1, *h1, *hin2, *w1a, *w1b, *w2a, *w2b;
    float* h2;
    cudaGetSymbolAddress((void**)&xb,   g_xb);
    cudaGetSymbolAddress((void**)&hin1, g_hin1);
    cudaGetSymbolAddress((void**)&h1,   g_h1);
    cudaGetSymbolAddress((void**)&hin2, g_hin2);
    cudaGetSymbolAddress((void**)&h2,   g_h2);
    cudaGetSymbolAddress((void**)&w1a,  g_w1a);
    cudaGetSymbolAddress((void**)&w1b,  g_w1b);
    cudaGetSymbolAddress((void**)&w2a,  g_w2a);
    cudaGetSymbolAddress((void**)&w2b,  g_w2b);

    cudaFuncSetAttribute(mlp_kernel<64, true>,
                         cudaFuncAttributeMaxDynamicSharedMemorySize, MLP_SMEM);
    cudaFuncSetAttribute(mlp_kernel<200, false>,
                         cudaFuncAttributeMaxDynamicSharedMemorySize, MLP_SMEM);

    const int TPB = 256;
    int nbEdges8 = (N_EDGES / 8 + TPB - 1) / TPB;
    int nbNodes = (N_NODES + TPB - 1) / TPB;
    int nbWarpNodes = (N_NODES * 32 + TPB - 1) / TPB;
    int mlp_grid = (N_NODES + 127) / 128;  // 782

    // CSR build + conversions
    convhist_kernel<<<CONV_BLOCKS + HIST_BLOCKS, TPB>>>(x, W1a, W1b, W2a, W2b, (const int4*)dst);
    scan_block_kernel<<<NB_SCAN, 1024>>>();
    scan_apply_kernel<<<nbNodes, TPB>>>();
    fill_kernel<<<nbEdges8, TPB>>>((const int4*)src, (const int4*)dst);

    // Layer 1
    agg64_kernel<<<nbWarpNodes, TPB>>>(xb, eps1, hin1);
    mlp_kernel<64, true><<<mlp_grid, 256, MLP_SMEM>>>(
        hin1, w1a, b1a, w1b, b1b, bn1g, bn1b, bn1m, bn1v, h1, N_NODES);

    // Layer 2
    agg200_kernel<<<nbWarpNodes, TPB>>>(h1, eps2, hin2);
    mlp_kernel<200, false><<<mlp_grid, 256, MLP_SMEM>>>(
        hin2, w2a, b2a, w2b, b2b, bn2g, bn2b, bn2m, bn2v, h2, N_NODES);

    // fused pooling + FC + log_softmax
    poolfc_kernel<<<N_GRAPHS, 256>>>(batch, Wfc, bfc, out);
}